// round 4
// baseline (speedup 1.0000x reference)
#include <cuda_runtime.h>
#include <cstdint>

#define N_TOK 4096
#define DDIM  1024
#define BK 16

// Scratch (device globals: allowed; no runtime allocation)
__device__ float g_Q[(size_t)N_TOK * DDIM];
__device__ float g_K[(size_t)N_TOK * DDIM];
__device__ float g_V[(size_t)N_TOK * DDIM];
__device__ float g_P[(size_t)N_TOK * N_TOK];
__device__ float g_rsum[N_TOK];

// Fragment-packed smem layout (words):
//  A region: 16 blocks (bm16 0..7, k8 0..1), block = 16x8 tf32 stored as
//            32 lanes x uint4 (a0,a1,a2,a3) -> 128 words/block, 2048 words total
//  B region: 32 blocks (bn8 0..15, k8 0..1), block = 8x8 tf32 stored as
//            32 lanes x uint2 (b0,b1) -> 64 words/block, 2048 words total
#define A_WORDS 2048
#define B_WORDS 2048
#define STAGE_WORDS (A_WORDS + B_WORDS)

__device__ __forceinline__ uint32_t f2tf32(float x) {
    uint32_t u;
    asm volatile("cvt.rna.tf32.f32 %0, %1;" : "=r"(u) : "f"(x));
    return u;
}

__device__ __forceinline__ void mma_tf32(float d[4], const uint32_t a[4], const uint32_t b[2]) {
    asm volatile(
        "mma.sync.aligned.m16n8k8.row.col.f32.tf32.tf32.f32 "
        "{%0,%1,%2,%3}, {%4,%5,%6,%7}, {%8,%9}, {%0,%1,%2,%3};\n"
        : "+f"(d[0]), "+f"(d[1]), "+f"(d[2]), "+f"(d[3])
        : "r"(a[0]), "r"(a[1]), "r"(a[2]), "r"(a[3]),
          "r"(b[0]), "r"(b[1]));
}

// ---- global -> registers (BK=16 slab of A[128xK] and B) ----
// B_DIRECT:  B is [N x K] row-major (K-matrix for Q@K^T).
// !B_DIRECT: B is [K x N] row-major (weights W, V).
template <bool B_DIRECT>
__device__ __forceinline__ void global_load(
    const float* __restrict__ A, const float* __restrict__ B,
    int lda, int ldb, int bm, int bn, int kt, int tid,
    float4 ra[2], float4 rb[2])
{
#pragma unroll
    for (int i = 0; i < 2; i++) {
        int f = tid + i * 256;           // 512 float4 per tile
        int row = f >> 2, c4 = f & 3;    // 128 rows x 4 float4 (16 floats)
        ra[i] = *reinterpret_cast<const float4*>(
            A + (size_t)(bm + row) * lda + (size_t)kt * BK + c4 * 4);
        if (B_DIRECT) {
            rb[i] = *reinterpret_cast<const float4*>(
                B + (size_t)(bn + row) * ldb + (size_t)kt * BK + c4 * 4);
        } else {
            int krow = f >> 5, nc4 = f & 31;  // 16 k-rows x 32 float4 (128 n)
            rb[i] = *reinterpret_cast<const float4*>(
                B + (size_t)((size_t)kt * BK + krow) * ldb + bn + nc4 * 4);
        }
    }
}

// ---- registers -> fragment-packed smem (tf32-rounded, scatter STS) ----
// aoff/boff are per-thread word offsets (j-stride: A=4 words, B_DIRECT=2, else=8)
template <bool B_DIRECT>
__device__ __forceinline__ void smem_store(
    uint32_t* st, const uint32_t aoff[2], const uint32_t boff[2],
    const float4 ra[2], const float4 rb[2])
{
#pragma unroll
    for (int i = 0; i < 2; i++) {
        uint32_t* p = st + aoff[i];
        p[0]  = f2tf32(ra[i].x);
        p[4]  = f2tf32(ra[i].y);
        p[8]  = f2tf32(ra[i].z);
        p[12] = f2tf32(ra[i].w);
        uint32_t* q = st + A_WORDS + boff[i];
        if (B_DIRECT) {
            q[0] = f2tf32(rb[i].x);
            q[2] = f2tf32(rb[i].y);
            q[4] = f2tf32(rb[i].z);
            q[6] = f2tf32(rb[i].w);
        } else {
            q[0]  = f2tf32(rb[i].x);
            q[8]  = f2tf32(rb[i].y);
            q[16] = f2tf32(rb[i].z);
            q[24] = f2tf32(rb[i].w);
        }
    }
}

// 128x128 CTA tile, 8 warps as 4(M) x 2(N), warp tile 32x64, double-buffered.
template <bool B_DIRECT>
__device__ __forceinline__ void gemm_main(
    const float* __restrict__ A, const float* __restrict__ B,
    int lda, int ldb, int kIters, int bm, int bn,
    uint32_t* smem, float (&acc)[2][8][4])
{
    const int tid = threadIdx.x;

    // ---- per-thread scatter-store offsets (constant across k) ----
    uint32_t aoff[2], boff[2];
#pragma unroll
    for (int i = 0; i < 2; i++) {
        int f = tid + i * 256;
        int r = f >> 2, c4 = f & 3;
        int g = r & 7, rowhalf = (r >> 3) & 1, bm16 = r >> 4;
        int k8 = c4 >> 1, h = c4 & 1;
        aoff[i] = (uint32_t)((bm16 * 2 + k8) * 128 + g * 16 + (rowhalf + 2 * h));
        if (B_DIRECT) {
            boff[i] = (uint32_t)(((r >> 3) * 2 + k8) * 64 + g * 8 + h);
        } else {
            int krow = f >> 5, n0 = (f & 31) * 4;
            boff[i] = (uint32_t)(((n0 >> 3) * 2 + (krow >> 3)) * 64 +
                                 ((n0 & 7) * 4 + (krow & 3)) * 2 + ((krow >> 2) & 1));
        }
    }

#pragma unroll
    for (int mi = 0; mi < 2; mi++)
#pragma unroll
        for (int ni = 0; ni < 8; ni++)
#pragma unroll
            for (int j = 0; j < 4; j++) acc[mi][ni][j] = 0.f;

    float4 ra[2], rb[2];
    global_load<B_DIRECT>(A, B, lda, ldb, bm, bn, 0, tid, ra, rb);
    smem_store<B_DIRECT>(smem, aoff, boff, ra, rb);
    __syncthreads();

    const int w = tid >> 5, lane = tid & 31;
    const int wm4 = w & 3;             // m-quadrant (rows wm4*32..+31)
    const int wn8 = (w >> 2) * 8;      // first bn8 block of this warp

    for (int kt = 0; kt < kIters; ++kt) {
        if (kt + 1 < kIters)
            global_load<B_DIRECT>(A, B, lda, ldb, bm, bn, kt + 1, tid, ra, rb);

        const uint32_t* sA = smem + (kt & 1) * STAGE_WORDS;
        const uint32_t* sB = sA + A_WORDS;

#pragma unroll
        for (int ks = 0; ks < 2; ks++) {
            uint4 af[2];
            uint2 bf[8];
#pragma unroll
            for (int mi = 0; mi < 2; mi++)
                af[mi] = *reinterpret_cast<const uint4*>(
                    sA + ((2 * wm4 + mi) * 2 + ks) * 128 + lane * 4);
#pragma unroll
            for (int ni = 0; ni < 8; ni++)
                bf[ni] = *reinterpret_cast<const uint2*>(
                    sB + ((wn8 + ni) * 2 + ks) * 64 + lane * 2);
#pragma unroll
            for (int mi = 0; mi < 2; mi++)
#pragma unroll
                for (int ni = 0; ni < 8; ni++)
                    mma_tf32(acc[mi][ni], reinterpret_cast<const uint32_t*>(&af[mi]),
                             reinterpret_cast<const uint32_t*>(&bf[ni]));
        }

        if (kt + 1 < kIters)
            smem_store<B_DIRECT>(smem + ((kt + 1) & 1) * STAGE_WORDS, aoff, boff, ra, rb);
        __syncthreads();
    }
}

// ---------- Kernel 1: Q/K/V = X @ W + b ----------
__global__ void __launch_bounds__(256, 2)
qkv_kernel(const float* __restrict__ x,
           const float* __restrict__ Wq, const float* __restrict__ bq,
           const float* __restrict__ Wk, const float* __restrict__ bk,
           const float* __restrict__ Wv, const float* __restrict__ bv)
{
    __shared__ uint32_t smem[2 * STAGE_WORDS];
    const float* W; const float* bias; float* O;
    if (blockIdx.z == 0)      { W = Wq; bias = bq; O = g_Q; }
    else if (blockIdx.z == 1) { W = Wk; bias = bk; O = g_K; }
    else                      { W = Wv; bias = bv; O = g_V; }

    const int bm = blockIdx.y * 128, bn = blockIdx.x * 128;
    float acc[2][8][4];
    gemm_main<false>(x, W, DDIM, DDIM, DDIM / BK, bm, bn, smem, acc);

    const int w = threadIdx.x >> 5, lane = threadIdx.x & 31;
    const int wm = (w & 3) * 32, wn = (w >> 2) * 64;
    const int gid = lane >> 2, tig = lane & 3;
#pragma unroll
    for (int mi = 0; mi < 2; mi++) {
        int r0 = bm + wm + mi * 16 + gid;
#pragma unroll
        for (int ni = 0; ni < 8; ni++) {
            int c = bn + wn + ni * 8 + 2 * tig;
            float b0 = bias[c], b1 = bias[c + 1];
            float2 v0 = make_float2(acc[mi][ni][0] + b0, acc[mi][ni][1] + b1);
            float2 v1 = make_float2(acc[mi][ni][2] + b0, acc[mi][ni][3] + b1);
            *reinterpret_cast<float2*>(&O[(size_t)r0 * DDIM + c]) = v0;
            *reinterpret_cast<float2*>(&O[(size_t)(r0 + 8) * DDIM + c]) = v1;
        }
    }
}

// ---------- Kernel 2: P = exp(tanh(Q @ K^T) / 32) ----------
__global__ void __launch_bounds__(256, 2)
score_kernel()
{
    __shared__ uint32_t smem[2 * STAGE_WORDS];
    const int bm = blockIdx.y * 128, bn = blockIdx.x * 128;
    float acc[2][8][4];
    gemm_main<true>(g_Q, g_K, DDIM, DDIM, DDIM / BK, bm, bn, smem, acc);

    const int w = threadIdx.x >> 5, lane = threadIdx.x & 31;
    const int wm = (w & 3) * 32, wn = (w >> 2) * 64;
    const int gid = lane >> 2, tig = lane & 3;
    const float sc = 0.03125f;  // 1/sqrt(1024)
#pragma unroll
    for (int mi = 0; mi < 2; mi++) {
        int r0 = bm + wm + mi * 16 + gid;
#pragma unroll
        for (int ni = 0; ni < 8; ni++) {
            int c = bn + wn + ni * 8 + 2 * tig;
            float e[4];
#pragma unroll
            for (int q = 0; q < 4; q++) {
                float t;
                asm("tanh.approx.f32 %0, %1;" : "=f"(t) : "f"(acc[mi][ni][q]));
                e[q] = __expf(t * sc);
            }
            *reinterpret_cast<float2*>(&g_P[(size_t)r0 * N_TOK + c]) = make_float2(e[0], e[1]);
            *reinterpret_cast<float2*>(&g_P[(size_t)(r0 + 8) * N_TOK + c]) = make_float2(e[2], e[3]);
        }
    }
}

// ---------- Kernel 3: row sums of P ----------
__global__ void __launch_bounds__(256)
rowsum_kernel()
{
    const int row = blockIdx.x;
    const float4* p = reinterpret_cast<const float4*>(g_P + (size_t)row * N_TOK);
    float s = 0.f;
#pragma unroll
    for (int i = 0; i < 4; i++) {
        float4 v = p[threadIdx.x + i * 256];
        s += (v.x + v.y) + (v.z + v.w);
    }
#pragma unroll
    for (int o = 16; o > 0; o >>= 1) s += __shfl_xor_sync(0xffffffffu, s, o);
    __shared__ float red[8];
    if ((threadIdx.x & 31) == 0) red[threadIdx.x >> 5] = s;
    __syncthreads();
    if (threadIdx.x < 8) {
        float t = red[threadIdx.x];
#pragma unroll
        for (int o = 4; o > 0; o >>= 1) t += __shfl_xor_sync(0xffu, t, o);
        if (threadIdx.x == 0) g_rsum[row] = t;
    }
}

// ---------- Kernel 4: out = (P @ V) / rsum ----------
__global__ void __launch_bounds__(256, 2)
pv_kernel(float* __restrict__ out)
{
    __shared__ uint32_t smem[2 * STAGE_WORDS];
    const int bm = blockIdx.y * 128, bn = blockIdx.x * 128;
    float acc[2][8][4];
    gemm_main<false>(g_P, g_V, N_TOK, DDIM, N_TOK / BK, bm, bn, smem, acc);

    const int w = threadIdx.x >> 5, lane = threadIdx.x & 31;
    const int wm = (w & 3) * 32, wn = (w >> 2) * 64;
    const int gid = lane >> 2, tig = lane & 3;
#pragma unroll
    for (int mi = 0; mi < 2; mi++) {
        int r0 = bm + wm + mi * 16 + gid;
        float inv0 = 1.0f / g_rsum[r0];
        float inv1 = 1.0f / g_rsum[r0 + 8];
#pragma unroll
        for (int ni = 0; ni < 8; ni++) {
            int c = bn + wn + ni * 8 + 2 * tig;
            float2 v0 = make_float2(acc[mi][ni][0] * inv0, acc[mi][ni][1] * inv0);
            float2 v1 = make_float2(acc[mi][ni][2] * inv1, acc[mi][ni][3] * inv1);
            *reinterpret_cast<float2*>(&out[(size_t)r0 * DDIM + c]) = v0;
            *reinterpret_cast<float2*>(&out[(size_t)(r0 + 8) * DDIM + c]) = v1;
        }
    }
}

extern "C" void kernel_launch(void* const* d_in, const int* in_sizes, int n_in,
                              void* d_out, int out_size)
{
    const float* x  = (const float*)d_in[0];
    const float* Wq = (const float*)d_in[1];
    const float* bq = (const float*)d_in[2];
    const float* Wk = (const float*)d_in[3];
    const float* bk = (const float*)d_in[4];
    const float* Wv = (const float*)d_in[5];
    const float* bv = (const float*)d_in[6];
    float* out = (float*)d_out;

    qkv_kernel  <<<dim3(DDIM / 128, N_TOK / 128, 3), 256>>>(x, Wq, bq, Wk, bk, Wv, bv);
    score_kernel<<<dim3(N_TOK / 128, N_TOK / 128),   256>>>();
    rowsum_kernel<<<N_TOK, 256>>>();
    pv_kernel   <<<dim3(DDIM / 128, N_TOK / 128),    256>>>(out);
}

// round 5
// speedup vs baseline: 2.0950x; 2.0950x over previous
#include <cuda_runtime.h>
#include <cstdint>

#define N_TOK 4096
#define DDIM  1024
#define BK 16

// Scratch (device globals; no runtime allocation)
__device__ float g_Q[(size_t)N_TOK * DDIM];
__device__ float g_K[(size_t)N_TOK * DDIM];
__device__ float g_V[(size_t)N_TOK * DDIM];
__device__ float g_Vt[(size_t)DDIM * N_TOK];       // V transposed [dim][token]
__device__ float g_Wt[3][(size_t)DDIM * DDIM];     // W transposed [out][in]
__device__ float g_P[(size_t)N_TOK * N_TOK];
__device__ float g_rsum[N_TOK];

// ---- pair-packed smem layout (uint2 units) ----
// Per matrix per stage: 2 planes (k0 = 0, 8), plane = 128 rows x 4 pairs + 1 pad = 513.
// Pair m' of row r in plane p holds tf32 cols (m, m+4) of k-half p, where
// m' = (m + 2*((r>>2)&1)) & 3. Conflict-free for LDS.64 loads and STS.64 stores.
#define PLANE_PAIRS 513
#define MAT_PAIRS   (2 * PLANE_PAIRS)   // 1026
#define STAGE_PAIRS (2 * MAT_PAIRS)     // 2052 (A then B)

__device__ __forceinline__ uint32_t f2tf32(float x) {
    uint32_t u;
    asm volatile("cvt.rna.tf32.f32 %0, %1;" : "=r"(u) : "f"(x));
    return u;
}

__device__ __forceinline__ void mma_tf32(float d[4], uint32_t a0, uint32_t a1, uint32_t a2,
                                         uint32_t a3, uint32_t b0, uint32_t b1) {
    asm volatile(
        "mma.sync.aligned.m16n8k8.row.col.f32.tf32.tf32.f32 "
        "{%0,%1,%2,%3}, {%4,%5,%6,%7}, {%8,%9}, {%0,%1,%2,%3};\n"
        : "+f"(d[0]), "+f"(d[1]), "+f"(d[2]), "+f"(d[3])
        : "r"(a0), "r"(a1), "r"(a2), "r"(a3), "r"(b0), "r"(b1));
}

// global -> registers: thread tid covers row = tid>>1, k-half = tid&1 (8 floats) of A and B
__device__ __forceinline__ void global_load(
    const float* __restrict__ A, const float* __restrict__ B,
    int lda, int ldb, int bm, int bn, int kt, int tid, float4 r[4])
{
    const int row = tid >> 1, half = tid & 1;
    const float* pa = A + (size_t)(bm + row) * lda + kt * BK + half * 8;
    r[0] = *reinterpret_cast<const float4*>(pa);
    r[1] = *reinterpret_cast<const float4*>(pa + 4);
    const float* pb = B + (size_t)(bn + row) * ldb + kt * BK + half * 8;
    r[2] = *reinterpret_cast<const float4*>(pb);
    r[3] = *reinterpret_cast<const float4*>(pb + 4);
}

// registers -> pair-packed smem (tf32-rounded), 8 STS.64 per thread, conflict-free
__device__ __forceinline__ void smem_store(uint2* stage, int tid, const float4 r[4])
{
    const int row = tid >> 1, half = tid & 1;
    const int sw2 = ((row >> 2) & 1) * 2;
    uint2* sa = stage + half * PLANE_PAIRS + row * 4;
    uint2* sb = sa + MAT_PAIRS;
    uint32_t a0 = f2tf32(r[0].x), a1 = f2tf32(r[0].y), a2 = f2tf32(r[0].z), a3 = f2tf32(r[0].w);
    uint32_t a4 = f2tf32(r[1].x), a5 = f2tf32(r[1].y), a6 = f2tf32(r[1].z), a7 = f2tf32(r[1].w);
    sa[(0 + sw2) & 3] = make_uint2(a0, a4);
    sa[(1 + sw2) & 3] = make_uint2(a1, a5);
    sa[(2 + sw2) & 3] = make_uint2(a2, a6);
    sa[(3 + sw2) & 3] = make_uint2(a3, a7);
    uint32_t b0 = f2tf32(r[2].x), b1 = f2tf32(r[2].y), b2 = f2tf32(r[2].z), b3 = f2tf32(r[2].w);
    uint32_t b4 = f2tf32(r[3].x), b5 = f2tf32(r[3].y), b6 = f2tf32(r[3].z), b7 = f2tf32(r[3].w);
    sb[(0 + sw2) & 3] = make_uint2(b0, b4);
    sb[(1 + sw2) & 3] = make_uint2(b1, b5);
    sb[(2 + sw2) & 3] = make_uint2(b2, b6);
    sb[(3 + sw2) & 3] = make_uint2(b3, b7);
}

// 128x128 CTA tile, 8 warps as 4(M) x 2(N), warp tile 32x64, double-buffered.
// A is [M x K] row-major, B is [N x K] row-major (always B_DIRECT now).
__device__ __forceinline__ void gemm_main(
    const float* __restrict__ A, const float* __restrict__ B,
    int lda, int ldb, int kIters, int bm, int bn,
    uint2* smem, float (&acc)[2][8][4])
{
    const int tid = threadIdx.x;

#pragma unroll
    for (int mi = 0; mi < 2; mi++)
#pragma unroll
        for (int ni = 0; ni < 8; ni++)
#pragma unroll
            for (int j = 0; j < 4; j++) acc[mi][ni][j] = 0.f;

    float4 r[4];
    global_load(A, B, lda, ldb, bm, bn, 0, tid, r);
    smem_store(smem, tid, r);
    __syncthreads();

    const int w = tid >> 5, lane = tid & 31;
    const int wm4 = w & 3;              // m quadrant: rows wm4*32..+31
    const int wn  = (w >> 2) * 64;      // n half
    const int gid = lane >> 2, tig = lane & 3;
    const int mp = (tig + 2 * ((gid >> 2) & 1)) & 3;   // swizzled pair index

    for (int kt = 0; kt < kIters; ++kt) {
        if (kt + 1 < kIters)
            global_load(A, B, lda, ldb, bm, bn, kt + 1, tid, r);

        const uint2* sA = smem + (kt & 1) * STAGE_PAIRS;
        const uint2* sB = sA + MAT_PAIRS;

#pragma unroll
        for (int ks = 0; ks < 2; ks++) {
            const uint2* pA = sA + ks * PLANE_PAIRS + mp;
            const uint2* pB = sB + ks * PLANE_PAIRS + mp;
            uint2 alo[2], ahi[2], bb[8];
#pragma unroll
            for (int mi = 0; mi < 2; mi++) {
                int rbase = wm4 * 32 + mi * 16 + gid;
                alo[mi] = pA[rbase * 4];
                ahi[mi] = pA[(rbase + 8) * 4];
            }
#pragma unroll
            for (int ni = 0; ni < 8; ni++)
                bb[ni] = pB[(wn + ni * 8 + gid) * 4];
#pragma unroll
            for (int mi = 0; mi < 2; mi++)
#pragma unroll
                for (int ni = 0; ni < 8; ni++)
                    mma_tf32(acc[mi][ni], alo[mi].x, ahi[mi].x, alo[mi].y, ahi[mi].y,
                             bb[ni].x, bb[ni].y);
        }

        if (kt + 1 < kIters)
            smem_store(smem + ((kt + 1) & 1) * STAGE_PAIRS, tid, r);
        __syncthreads();
    }
}

// ---------- transpose: out[c][r] = in[r][c]; out selected by index ----------
__global__ void __launch_bounds__(256)
transpose_kernel(const float* __restrict__ in, int out_idx, int rows, int cols)
{
    __shared__ float t[32][33];
    const float* src = (out_idx == 3) ? g_V : in;
    float* dst = (out_idx == 3) ? g_Vt : g_Wt[out_idx];
    const int bx = blockIdx.x * 32, by = blockIdx.y * 32;
    const int tx = threadIdx.x & 31, ty = threadIdx.x >> 5;  // 32 x 8
#pragma unroll
    for (int i = 0; i < 32; i += 8)
        t[ty + i][tx] = src[(size_t)(by + ty + i) * cols + bx + tx];
    __syncthreads();
#pragma unroll
    for (int i = 0; i < 32; i += 8)
        dst[(size_t)(bx + ty + i) * rows + by + tx] = t[tx][ty + i];
}

// ---------- Kernel 1: Q/K/V = X @ W + b ----------
__global__ void __launch_bounds__(256, 2)
qkv_kernel(const float* __restrict__ x,
           const float* __restrict__ bq, const float* __restrict__ bk,
           const float* __restrict__ bv)
{
    __shared__ uint2 smem[2 * STAGE_PAIRS];
    const float* bias; float* O;
    if (blockIdx.z == 0)      { bias = bq; O = g_Q; }
    else if (blockIdx.z == 1) { bias = bk; O = g_K; }
    else                      { bias = bv; O = g_V; }
    const float* W = g_Wt[blockIdx.z];

    const int bm = blockIdx.y * 128, bn = blockIdx.x * 128;
    float acc[2][8][4];
    gemm_main(x, W, DDIM, DDIM, DDIM / BK, bm, bn, smem, acc);

    const int w = threadIdx.x >> 5, lane = threadIdx.x & 31;
    const int wm = (w & 3) * 32, wn = (w >> 2) * 64;
    const int gid = lane >> 2, tig = lane & 3;
#pragma unroll
    for (int mi = 0; mi < 2; mi++) {
        int r0 = bm + wm + mi * 16 + gid;
#pragma unroll
        for (int ni = 0; ni < 8; ni++) {
            int c = bn + wn + ni * 8 + 2 * tig;
            float b0 = bias[c], b1 = bias[c + 1];
            float2 v0 = make_float2(acc[mi][ni][0] + b0, acc[mi][ni][1] + b1);
            float2 v1 = make_float2(acc[mi][ni][2] + b0, acc[mi][ni][3] + b1);
            *reinterpret_cast<float2*>(&O[(size_t)r0 * DDIM + c]) = v0;
            *reinterpret_cast<float2*>(&O[(size_t)(r0 + 8) * DDIM + c]) = v1;
        }
    }
}

// ---------- Kernel 2: P = exp(tanh(Q @ K^T) / 32) ----------
__global__ void __launch_bounds__(256, 2)
score_kernel()
{
    __shared__ uint2 smem[2 * STAGE_PAIRS];
    const int bm = blockIdx.y * 128, bn = blockIdx.x * 128;
    float acc[2][8][4];
    gemm_main(g_Q, g_K, DDIM, DDIM, DDIM / BK, bm, bn, smem, acc);

    const int w = threadIdx.x >> 5, lane = threadIdx.x & 31;
    const int wm = (w & 3) * 32, wn = (w >> 2) * 64;
    const int gid = lane >> 2, tig = lane & 3;
    const float sc = 0.03125f;  // 1/sqrt(1024)
#pragma unroll
    for (int mi = 0; mi < 2; mi++) {
        int r0 = bm + wm + mi * 16 + gid;
#pragma unroll
        for (int ni = 0; ni < 8; ni++) {
            int c = bn + wn + ni * 8 + 2 * tig;
            float e[4];
#pragma unroll
            for (int q = 0; q < 4; q++) {
                float t;
                asm("tanh.approx.f32 %0, %1;" : "=f"(t) : "f"(acc[mi][ni][q]));
                e[q] = __expf(t * sc);
            }
            *reinterpret_cast<float2*>(&g_P[(size_t)r0 * N_TOK + c]) = make_float2(e[0], e[1]);
            *reinterpret_cast<float2*>(&g_P[(size_t)(r0 + 8) * N_TOK + c]) = make_float2(e[2], e[3]);
        }
    }
}

// ---------- Kernel 3: row sums of P ----------
__global__ void __launch_bounds__(256)
rowsum_kernel()
{
    const int row = blockIdx.x;
    const float4* p = reinterpret_cast<const float4*>(g_P + (size_t)row * N_TOK);
    float s = 0.f;
#pragma unroll
    for (int i = 0; i < 4; i++) {
        float4 v = p[threadIdx.x + i * 256];
        s += (v.x + v.y) + (v.z + v.w);
    }
#pragma unroll
    for (int o = 16; o > 0; o >>= 1) s += __shfl_xor_sync(0xffffffffu, s, o);
    __shared__ float red[8];
    if ((threadIdx.x & 31) == 0) red[threadIdx.x >> 5] = s;
    __syncthreads();
    if (threadIdx.x < 8) {
        float t = red[threadIdx.x];
#pragma unroll
        for (int o = 4; o > 0; o >>= 1) t += __shfl_xor_sync(0xffu, t, o);
        if (threadIdx.x == 0) g_rsum[row] = t;
    }
}

// ---------- Kernel 4: out = (P @ V) / rsum ----------
__global__ void __launch_bounds__(256, 2)
pv_kernel(float* __restrict__ out)
{
    __shared__ uint2 smem[2 * STAGE_PAIRS];
    const int bm = blockIdx.y * 128, bn = blockIdx.x * 128;
    float acc[2][8][4];
    gemm_main(g_P, g_Vt, N_TOK, N_TOK, N_TOK / BK, bm, bn, smem, acc);

    const int w = threadIdx.x >> 5, lane = threadIdx.x & 31;
    const int wm = (w & 3) * 32, wn = (w >> 2) * 64;
    const int gid = lane >> 2, tig = lane & 3;
#pragma unroll
    for (int mi = 0; mi < 2; mi++) {
        int r0 = bm + wm + mi * 16 + gid;
        float inv0 = 1.0f / g_rsum[r0];
        float inv1 = 1.0f / g_rsum[r0 + 8];
#pragma unroll
        for (int ni = 0; ni < 8; ni++) {
            int c = bn + wn + ni * 8 + 2 * tig;
            float2 v0 = make_float2(acc[mi][ni][0] * inv0, acc[mi][ni][1] * inv0);
            float2 v1 = make_float2(acc[mi][ni][2] * inv1, acc[mi][ni][3] * inv1);
            *reinterpret_cast<float2*>(&out[(size_t)r0 * DDIM + c]) = v0;
            *reinterpret_cast<float2*>(&out[(size_t)(r0 + 8) * DDIM + c]) = v1;
        }
    }
}

extern "C" void kernel_launch(void* const* d_in, const int* in_sizes, int n_in,
                              void* d_out, int out_size)
{
    const float* x  = (const float*)d_in[0];
    const float* Wq = (const float*)d_in[1];
    const float* bq = (const float*)d_in[2];
    const float* Wk = (const float*)d_in[3];
    const float* bk = (const float*)d_in[4];
    const float* Wv = (const float*)d_in[5];
    const float* bv = (const float*)d_in[6];
    float* out = (float*)d_out;

    transpose_kernel<<<dim3(32, 32), 256>>>(Wq, 0, DDIM, DDIM);
    transpose_kernel<<<dim3(32, 32), 256>>>(Wk, 1, DDIM, DDIM);
    transpose_kernel<<<dim3(32, 32), 256>>>(Wv, 2, DDIM, DDIM);
    qkv_kernel<<<dim3(DDIM / 128, N_TOK / 128, 3), 256>>>(x, bq, bk, bv);
    transpose_kernel<<<dim3(DDIM / 32, N_TOK / 32), 256>>>(nullptr, 3, N_TOK, DDIM);
    score_kernel<<<dim3(N_TOK / 128, N_TOK / 128), 256>>>();
    rowsum_kernel<<<N_TOK, 256>>>();
    pv_kernel<<<dim3(DDIM / 128, N_TOK / 128), 256>>>(out);
}